// round 7
// baseline (speedup 1.0000x reference)
#include <cuda_runtime.h>

#define LN_EPS 1e-12f

// Precomputed LN(W_rel): 130 x 64 floats, built once by k_prep.
__device__ float g_lnrel[130 * 64];

struct SmemU {
    union {
        struct {                        // embd2 role
            float tab[130 * 64];        // 33280 B  LN(W_rel) fp32
            int   sid[2][512];          // 4096 B   float4 offsets, -1 = diag
            int   stype[512];           // 2048 B
        } e2;
        struct {                        // compute role
            float sx[8][768];           // 24576 B  pre-LN embd1 rows
            float sWd[64][65];          // 16640 B  W_diag chunk [d][k]
            float wsum[8], wsq[8];
            float stat[2];
        } e1;
    };
};

// ---------------------------------------------------------------------------
// Prep: one block per W_rel row, 64 threads; LN -> g_lnrel.
// ---------------------------------------------------------------------------
__global__ void k_prep(const float* __restrict__ W_rel) {
    int blk = blockIdx.x, t = threadIdx.x;
    __shared__ float red[4];

    float x = W_rel[blk * 64 + t];
    float s = x, q = x * x;
    #pragma unroll
    for (int o = 16; o; o >>= 1) {
        s += __shfl_down_sync(0xffffffffu, s, o);
        q += __shfl_down_sync(0xffffffffu, q, o);
    }
    if ((t & 31) == 0) { red[(t >> 5) * 2] = s; red[(t >> 5) * 2 + 1] = q; }
    __syncthreads();
    float mean = (red[0] + red[2]) * (1.0f / 64.0f);
    float var  = (red[1] + red[3]) * (1.0f / 64.0f) - mean * mean;
    float inv  = rsqrtf(var + LN_EPS);
    g_lnrel[blk * 64 + t] = (x - mean) * inv;
}

// ---------------------------------------------------------------------------
__global__ void __launch_bounds__(256, 5) k_fused(
    const int* __restrict__ tok, const int* __restrict__ tty,
    const float* __restrict__ Wword, const float* __restrict__ Wtype,
    const float* __restrict__ Wabs,  const float* __restrict__ Wrel,
    const float* __restrict__ Wglob, const float* __restrict__ Wdiag,
    const float* __restrict__ bdiag,
    float* __restrict__ out0, float* __restrict__ out1,
    float* __restrict__ out2) {

    __shared__ SmemU sm;
    const int bid  = blockIdx.x;
    const int t    = threadIdx.x;
    const int warp = t >> 5, lane = t & 31;

    if ((bid % 5) != 4) {
        // ============ embd2 role: 2048 blocks, 2 rows each ==================
        const int eid = bid - bid / 5;
        const int R0  = eid * 2;                     // rows R0, R0+1 (same batch)
        const int b   = R0 >> 9;
        const int i0  = R0 & 511;

        // stage precomputed table: perfectly coalesced float4 copy from L2
        {
            const float4* src = reinterpret_cast<const float4*>(g_lnrel);
            float4* dst = reinterpret_cast<float4*>(sm.e2.tab);
            #pragma unroll
            for (int e = t; e < 130 * 16; e += 256) dst[e] = src[e];
        }
        for (int j = t; j < 512; j += 256) sm.e2.stype[j] = tty[b * 512 + j];
        __syncthreads();

        const int ti0 = sm.e2.stype[i0];
        const int ti1 = sm.e2.stype[i0 + 1];
        for (int j = t; j < 512; j += 256) {
            int tj = sm.e2.stype[j];
            #pragma unroll
            for (int rr = 0; rr < 2; rr++) {
                int i  = i0 + rr;
                int ti = rr ? ti1 : ti0;
                int id;
                if (j == i)            id = -1;              // diag: skip
                else if (i == 0)       id = 128;
                else if (j == 0)       id = 129;
                else if (tj != ti)     id = 64;
                else {
                    int d = i - j;
                    id = (d > 0) ? 128 - min(d, 63) : min(-d, 63);
                }
                sm.e2.sid[rr][j] = (id < 0) ? -1 : (id << 4);  // float4 offset
            }
        }
        __syncthreads();

        const float4* tb4 = reinterpret_cast<const float4*>(sm.e2.tab);
        float4* outp = reinterpret_cast<float4*>(out2) + (size_t)R0 * (512 * 16);
        const int* sidp = &sm.e2.sid[0][0];
        #pragma unroll 4
        for (int e = t; e < 2 * 512 * 16; e += 256) {
            int jr = e >> 4;                      // rr*512 + j
            int d4 = e & 15;
            int s  = sidp[jr];
            if (s >= 0) __stcs(&outp[e], tb4[s + d4]);
        }
        return;
    }

    // ============ compute role: 512 blocks, 8 rows each =====================
    const int cid  = bid / 5;
    const int row0 = cid * 8;

    // out0 duty: blocks 0..7 LN 8 rows of W_glob each, broadcast x8 batches
    if (cid < 8) {
        int g = cid * 8 + warp;
        float x0 = Wglob[g * 64 + lane];
        float x1 = Wglob[g * 64 + 32 + lane];
        float s = x0 + x1, q = x0 * x0 + x1 * x1;
        #pragma unroll
        for (int o = 16; o; o >>= 1) {
            s += __shfl_xor_sync(0xffffffffu, s, o);
            q += __shfl_xor_sync(0xffffffffu, q, o);
        }
        float mean = s * (1.0f / 64.0f);
        float inv  = rsqrtf(q * (1.0f / 64.0f) - mean * mean + LN_EPS);
        float v0 = (x0 - mean) * inv, v1 = (x1 - mean) * inv;
        #pragma unroll
        for (int bb = 0; bb < 8; bb++) {
            out0[(bb * 64 + g) * 64 + lane]      = v0;
            out0[(bb * 64 + g) * 64 + 32 + lane] = v1;
        }
    }

    // ---- phase 1: gather + LN embd1 (8 rows) ----
    for (int r = 0; r < 8; r++) {
        int row = row0 + r;
        int s   = row & 511;
        int tk  = tok[row], ty = tty[row];
        const float* pw = Wword + (size_t)tk * 768;
        const float* pt = Wtype + (size_t)ty * 768;
        const float* pa = Wabs  + (size_t)s  * 768;
        float v0 = pw[t      ] + pt[t      ] + pa[t      ];
        float v1 = pw[t + 256] + pt[t + 256] + pa[t + 256];
        float v2 = pw[t + 512] + pt[t + 512] + pa[t + 512];
        sm.e1.sx[r][t] = v0; sm.e1.sx[r][t + 256] = v1; sm.e1.sx[r][t + 512] = v2;

        float s1 = v0 + v1 + v2;
        float q1 = v0 * v0 + v1 * v1 + v2 * v2;
        #pragma unroll
        for (int o = 16; o; o >>= 1) {
            s1 += __shfl_down_sync(0xffffffffu, s1, o);
            q1 += __shfl_down_sync(0xffffffffu, q1, o);
        }
        if (lane == 0) { sm.e1.wsum[warp] = s1; sm.e1.wsq[warp] = q1; }
        __syncthreads();
        if (t == 0) {
            float S = 0.f, Q = 0.f;
            #pragma unroll
            for (int w = 0; w < 8; w++) { S += sm.e1.wsum[w]; Q += sm.e1.wsq[w]; }
            float mean = S * (1.0f / 768.0f);
            float var  = Q * (1.0f / 768.0f) - mean * mean;
            sm.e1.stat[0] = mean; sm.e1.stat[1] = rsqrtf(var + LN_EPS);
        }
        __syncthreads();
        float mean = sm.e1.stat[0], inv = sm.e1.stat[1];
        float* o = out1 + (size_t)row * 768;
        __stcs(&o[t      ], (v0 - mean) * inv);
        __stcs(&o[t + 256], (v1 - mean) * inv);
        __stcs(&o[t + 512], (v2 - mean) * inv);
        __syncthreads();
    }

    // ---- phase 2: diag GEMV, warp-per-row, 64-k chunks, [d][k] layout ----
    float acc0 = 0.f, acc1 = 0.f;
    for (int c = 0; c < 12; c++) {
        __syncthreads();
        for (int e = t; e < 64 * 64; e += 256) {
            int d = e >> 6, k = e & 63;
            sm.e1.sWd[d][k] = Wdiag[(size_t)d * 768 + c * 64 + k];
        }
        __syncthreads();
        #pragma unroll 16
        for (int kk = 0; kk < 64; kk++) {
            float xv = sm.e1.sx[warp][c * 64 + kk];
            acc0 += xv * sm.e1.sWd[lane][kk];
            acc1 += xv * sm.e1.sWd[lane + 32][kk];
        }
    }

    {
        float y0 = acc0 + Wrel[lane]      + bdiag[lane];
        float y1 = acc1 + Wrel[lane + 32] + bdiag[lane + 32];
        float S = y0 + y1, Q = y0 * y0 + y1 * y1;
        #pragma unroll
        for (int o = 16; o; o >>= 1) {
            S += __shfl_xor_sync(0xffffffffu, S, o);
            Q += __shfl_xor_sync(0xffffffffu, Q, o);
        }
        float mean = S * (1.0f / 64.0f);
        float inv  = rsqrtf(Q * (1.0f / 64.0f) - mean * mean + LN_EPS);
        int row = row0 + warp;
        int s   = row & 511;
        float* od = out2 + ((size_t)row * 512 + s) * 64;
        od[lane]      = (y0 - mean) * inv;
        od[lane + 32] = (y1 - mean) * inv;
    }
}

// ---------------------------------------------------------------------------
extern "C" void kernel_launch(void* const* d_in, const int* in_sizes, int n_in,
                              void* d_out, int out_size) {
    const int*   tok   = (const int*)d_in[0];
    const int*   tty   = (const int*)d_in[1];
    const float* Wword = (const float*)d_in[2];
    const float* Wtype = (const float*)d_in[3];
    const float* Wabs  = (const float*)d_in[4];
    const float* Wrel  = (const float*)d_in[5];
    const float* Wglob = (const float*)d_in[6];
    const float* Wdiag = (const float*)d_in[7];
    const float* bdiag = (const float*)d_in[8];

    float* out  = (float*)d_out;
    float* out0 = out;                      // [8,64,64]
    float* out1 = out0 + 8 * 64 * 64;       // [8,512,768]
    float* out2 = out1 + 8 * 512 * 768;     // [8,512,512,64]

    k_prep <<<130, 64>>>(Wrel);
    k_fused<<<2560, 256>>>(tok, tty, Wword, Wtype, Wabs, Wrel, Wglob, Wdiag,
                           bdiag, out0, out1, out2);
}

// round 8
// speedup vs baseline: 1.4977x; 1.4977x over previous
#include <cuda_runtime.h>

#define LN_EPS 1e-12f

struct SmemU {
    union {
        struct {                       // embd2 role
            float lnrel[130 * 64];     // 33280 B
            int   sid[2][512];         // 4096 B
            int   stype[512];          // 2048 B
        } e2;
        struct {                       // compute role
            float sx[8][768];          // 24576 B
            float sWd[64][65];         // 16640 B
            float wsum[8], wsq[8];
            float stat[2];
        } e1;
    };
};

__global__ void __launch_bounds__(256) k_fused(
    const int* __restrict__ tok, const int* __restrict__ tty,
    const float* __restrict__ Wword, const float* __restrict__ Wtype,
    const float* __restrict__ Wabs,  const float* __restrict__ Wrel,
    const float* __restrict__ Wglob, const float* __restrict__ Wdiag,
    const float* __restrict__ bdiag,
    float* __restrict__ out0, float* __restrict__ out1,
    float* __restrict__ out2) {

    __shared__ SmemU sm;
    const int bid  = blockIdx.x;
    const int t    = threadIdx.x;
    const int warp = t >> 5, lane = t & 31;

    if ((bid % 5) != 4) {
        // ==================== embd2 role: 2048 blocks, 2 rows each =========
        const int eid = bid - bid / 5;
        const int R0  = eid * 2;            // global rows R0, R0+1 (same batch)
        const int b   = R0 >> 9;
        const int i0  = R0 & 511;

        // LN(W_rel) computed locally: warp-per-row, 17 passes (R2-proven)
        for (int p = 0; p < 17; p++) {
            int row = p * 8 + warp;
            if (row < 130) {
                float x0 = Wrel[row * 64 + lane];
                float x1 = Wrel[row * 64 + 32 + lane];
                float s = x0 + x1, q = x0 * x0 + x1 * x1;
                #pragma unroll
                for (int o = 16; o; o >>= 1) {
                    s += __shfl_xor_sync(0xffffffffu, s, o);
                    q += __shfl_xor_sync(0xffffffffu, q, o);
                }
                float mean = s * (1.0f / 64.0f);
                float inv  = rsqrtf(q * (1.0f / 64.0f) - mean * mean + LN_EPS);
                sm.e2.lnrel[row * 64 + lane]      = (x0 - mean) * inv;
                sm.e2.lnrel[row * 64 + 32 + lane] = (x1 - mean) * inv;
            }
        }
        for (int j = t; j < 512; j += 256) sm.e2.stype[j] = tty[b * 512 + j];
        __syncthreads();

        for (int rr = 0; rr < 2; rr++) {
            int i  = i0 + rr;
            int ti = sm.e2.stype[i];
            for (int j = t; j < 512; j += 256) {
                int id;
                if (j == i)                      id = -1;          // diag: skip
                else if (i == 0)                 id = 128;
                else if (j == 0)                 id = 129;
                else if (sm.e2.stype[j] != ti)   id = 64;
                else {
                    int d = i - j;
                    id = (d > 0) ? 128 - min(d, 63) : min(-d, 63);
                }
                sm.e2.sid[rr][j] = (id < 0) ? -1 : (id << 4);
            }
        }
        __syncthreads();

        const float4* ln4 = reinterpret_cast<const float4*>(sm.e2.lnrel);
        float4* outp = reinterpret_cast<float4*>(out2) + (size_t)R0 * (512 * 16);
        const int* sidp = &sm.e2.sid[0][0];
        #pragma unroll 8
        for (int e = t; e < 2 * 512 * 16; e += 256) {
            int jr = e >> 4;
            int d4 = e & 15;
            int s  = sidp[jr];
            if (s >= 0) __stcs(&outp[e], ln4[s + d4]);
        }
        return;
    }

    // ==================== compute role: 512 blocks, 8 rows each ============
    const int cid  = bid / 5;
    const int row0 = cid * 8;

    // out0 duty: blocks 0..7 LN 8 rows of W_glob each, broadcast x8 batches
    if (cid < 8) {
        int g = cid * 8 + warp;
        float x0 = Wglob[g * 64 + lane];
        float x1 = Wglob[g * 64 + 32 + lane];
        float s = x0 + x1, q = x0 * x0 + x1 * x1;
        #pragma unroll
        for (int o = 16; o; o >>= 1) {
            s += __shfl_xor_sync(0xffffffffu, s, o);
            q += __shfl_xor_sync(0xffffffffu, q, o);
        }
        float mean = s * (1.0f / 64.0f);
        float inv  = rsqrtf(q * (1.0f / 64.0f) - mean * mean + LN_EPS);
        float v0 = (x0 - mean) * inv, v1 = (x1 - mean) * inv;
        #pragma unroll
        for (int bb = 0; bb < 8; bb++) {
            out0[(bb * 64 + g) * 64 + lane]      = v0;
            out0[(bb * 64 + g) * 64 + 32 + lane] = v1;
        }
    }

    // ---- phase 1: gather + LN embd1 (8 rows) ----
    for (int r = 0; r < 8; r++) {
        int row = row0 + r;
        int s   = row & 511;
        int tk  = tok[row], ty = tty[row];
        const float* pw = Wword + (size_t)tk * 768;
        const float* pt = Wtype + (size_t)ty * 768;
        const float* pa = Wabs  + (size_t)s  * 768;
        float v0 = pw[t      ] + pt[t      ] + pa[t      ];
        float v1 = pw[t + 256] + pt[t + 256] + pa[t + 256];
        float v2 = pw[t + 512] + pt[t + 512] + pa[t + 512];
        sm.e1.sx[r][t] = v0; sm.e1.sx[r][t + 256] = v1; sm.e1.sx[r][t + 512] = v2;

        float s1 = v0 + v1 + v2;
        float q1 = v0 * v0 + v1 * v1 + v2 * v2;
        #pragma unroll
        for (int o = 16; o; o >>= 1) {
            s1 += __shfl_down_sync(0xffffffffu, s1, o);
            q1 += __shfl_down_sync(0xffffffffu, q1, o);
        }
        if (lane == 0) { sm.e1.wsum[warp] = s1; sm.e1.wsq[warp] = q1; }
        __syncthreads();
        if (t == 0) {
            float S = 0.f, Q = 0.f;
            #pragma unroll
            for (int w = 0; w < 8; w++) { S += sm.e1.wsum[w]; Q += sm.e1.wsq[w]; }
            float mean = S * (1.0f / 768.0f);
            float var  = Q * (1.0f / 768.0f) - mean * mean;
            sm.e1.stat[0] = mean; sm.e1.stat[1] = rsqrtf(var + LN_EPS);
        }
        __syncthreads();
        float mean = sm.e1.stat[0], inv = sm.e1.stat[1];
        float* o = out1 + (size_t)row * 768;
        o[t      ] = (v0 - mean) * inv;
        o[t + 256] = (v1 - mean) * inv;
        o[t + 512] = (v2 - mean) * inv;
        __syncthreads();
    }

    // ---- phase 2: diag GEMV, warp-per-row, [d][k] layout ----
    float acc0 = 0.f, acc1 = 0.f;
    for (int c = 0; c < 12; c++) {
        __syncthreads();
        for (int e = t; e < 64 * 64; e += 256) {
            int d = e >> 6, k = e & 63;
            sm.e1.sWd[d][k] = Wdiag[(size_t)d * 768 + c * 64 + k];
        }
        __syncthreads();
        #pragma unroll 16
        for (int kk = 0; kk < 64; kk++) {
            float xv = sm.e1.sx[warp][c * 64 + kk];
            acc0 += xv * sm.e1.sWd[lane][kk];
            acc1 += xv * sm.e1.sWd[lane + 32][kk];
        }
    }

    {
        float y0 = acc0 + Wrel[lane]      + bdiag[lane];
        float y1 = acc1 + Wrel[lane + 32] + bdiag[lane + 32];
        float S = y0 + y1, Q = y0 * y0 + y1 * y1;
        #pragma unroll
        for (int o = 16; o; o >>= 1) {
            S += __shfl_xor_sync(0xffffffffu, S, o);
            Q += __shfl_xor_sync(0xffffffffu, Q, o);
        }
        float mean = S * (1.0f / 64.0f);
        float inv  = rsqrtf(Q * (1.0f / 64.0f) - mean * mean + LN_EPS);
        int row = row0 + warp;
        int s   = row & 511;
        float* od = out2 + ((size_t)row * 512 + s) * 64;
        od[lane]      = (y0 - mean) * inv;
        od[lane + 32] = (y1 - mean) * inv;
    }
}

// ---------------------------------------------------------------------------
extern "C" void kernel_launch(void* const* d_in, const int* in_sizes, int n_in,
                              void* d_out, int out_size) {
    const int*   tok   = (const int*)d_in[0];
    const int*   tty   = (const int*)d_in[1];
    const float* Wword = (const float*)d_in[2];
    const float* Wtype = (const float*)d_in[3];
    const float* Wabs  = (const float*)d_in[4];
    const float* Wrel  = (const float*)d_in[5];
    const float* Wglob = (const float*)d_in[6];
    const float* Wdiag = (const float*)d_in[7];
    const float* bdiag = (const float*)d_in[8];

    float* out  = (float*)d_out;
    float* out0 = out;                      // [8,64,64]
    float* out1 = out0 + 8 * 64 * 64;       // [8,512,768]
    float* out2 = out1 + 8 * 512 * 768;     // [8,512,512,64]

    k_fused<<<2560, 256>>>(tok, tty, Wword, Wtype, Wabs, Wrel, Wglob, Wdiag,
                           bdiag, out0, out1, out2);
}

// round 9
// speedup vs baseline: 1.6744x; 1.1179x over previous
#include <cuda_runtime.h>

#define LN_EPS 1e-12f

struct SmemU {
    union {
        struct {                       // embd2 role
            float lnrel[130 * 64];     // 33280 B
            int   sid[2][512];         // 4096 B
            int   stype[512];          // 2048 B
        } e2;
        struct {                       // compute role
            float sx[8][768];          // 24576 B
            union {
                float sWd[64][65];     // 16640 B
                float sred[8][8][64];  // 16384 B
            };
            float sy[8][64];           // 2048 B
            float wsum[8], wsq[8];
            float stat[2];
        } e1;
    };
};

__global__ void __launch_bounds__(256) k_fused(
    const int* __restrict__ tok, const int* __restrict__ tty,
    const float* __restrict__ Wword, const float* __restrict__ Wtype,
    const float* __restrict__ Wabs,  const float* __restrict__ Wrel,
    const float* __restrict__ Wglob, const float* __restrict__ Wdiag,
    const float* __restrict__ bdiag,
    float* __restrict__ out0, float* __restrict__ out1,
    float* __restrict__ out2) {

    __shared__ SmemU sm;
    const int bid  = blockIdx.x;
    const int t    = threadIdx.x;
    const int warp = t >> 5, lane = t & 31;

    if ((bid % 5) != 4) {
        // ==================== embd2 role: 2048 blocks, 2 rows each =========
        const int eid = bid - bid / 5;
        const int R0  = eid * 2;            // rows R0, R0+1 (same batch)
        const int b   = R0 >> 9;
        const int i0  = R0 & 511;

        // LN(W_rel) table: warp-per-row, 17 passes (R2-proven)
        for (int p = 0; p < 17; p++) {
            int row = p * 8 + warp;
            if (row < 130) {
                float x0 = Wrel[row * 64 + lane];
                float x1 = Wrel[row * 64 + 32 + lane];
                float s = x0 + x1, q = x0 * x0 + x1 * x1;
                #pragma unroll
                for (int o = 16; o; o >>= 1) {
                    s += __shfl_xor_sync(0xffffffffu, s, o);
                    q += __shfl_xor_sync(0xffffffffu, q, o);
                }
                float mean = s * (1.0f / 64.0f);
                float inv  = rsqrtf(q * (1.0f / 64.0f) - mean * mean + LN_EPS);
                sm.e2.lnrel[row * 64 + lane]      = (x0 - mean) * inv;
                sm.e2.lnrel[row * 64 + 32 + lane] = (x1 - mean) * inv;
            }
        }
        for (int j = t; j < 512; j += 256) sm.e2.stype[j] = tty[b * 512 + j];
        __syncthreads();

        for (int rr = 0; rr < 2; rr++) {
            int i  = i0 + rr;
            int ti = sm.e2.stype[i];
            for (int j = t; j < 512; j += 256) {
                int id;
                if (j == i)                      id = -1;          // diag: skip
                else if (i == 0)                 id = 128;
                else if (j == 0)                 id = 129;
                else if (sm.e2.stype[j] != ti)   id = 64;
                else {
                    int d = i - j;
                    id = (d > 0) ? 128 - min(d, 63) : min(-d, 63);
                }
                sm.e2.sid[rr][j] = (id < 0) ? -1 : (id << 4);      // float4 off
            }
        }
        __syncthreads();

        // ---- hot loop: explicit 4-wide batching for store-stream MLP ----
        const float4* ln4 = reinterpret_cast<const float4*>(sm.e2.lnrel);
        float4* outp = reinterpret_cast<float4*>(out2) + (size_t)R0 * (512 * 16);
        const int* sidp = &sm.e2.sid[0][0];
        const int d4  = t & 15;             // loop-invariant
        const int jr0 = t >> 4;             // 0..15
        #pragma unroll 4
        for (int g = 0; g < 16; g++) {
            int base = g * 64 + jr0;        // jr for u=0; +16 per u
            int s0 = sidp[base];
            int s1 = sidp[base + 16];
            int s2 = sidp[base + 32];
            int s3 = sidp[base + 48];
            float4 v0 = ln4[max(s0, 0) + d4];
            float4 v1 = ln4[max(s1, 0) + d4];
            float4 v2 = ln4[max(s2, 0) + d4];
            float4 v3 = ln4[max(s3, 0) + d4];
            float4* o = outp + base * 16 + d4;
            if (s0 >= 0) __stcs(o,              v0);
            if (s1 >= 0) __stcs(o + 16 * 16,    v1);
            if (s2 >= 0) __stcs(o + 32 * 16,    v2);
            if (s3 >= 0) __stcs(o + 48 * 16,    v3);
        }
        return;
    }

    // ==================== compute role: 512 blocks, 8 rows each ============
    const int cid  = bid / 5;
    const int row0 = cid * 8;

    // out0 duty: blocks 0..7 LN 8 rows of W_glob each, broadcast x8 batches
    if (cid < 8) {
        int g = cid * 8 + warp;
        float x0 = Wglob[g * 64 + lane];
        float x1 = Wglob[g * 64 + 32 + lane];
        float s = x0 + x1, q = x0 * x0 + x1 * x1;
        #pragma unroll
        for (int o = 16; o; o >>= 1) {
            s += __shfl_xor_sync(0xffffffffu, s, o);
            q += __shfl_xor_sync(0xffffffffu, q, o);
        }
        float mean = s * (1.0f / 64.0f);
        float inv  = rsqrtf(q * (1.0f / 64.0f) - mean * mean + LN_EPS);
        float v0 = (x0 - mean) * inv, v1 = (x1 - mean) * inv;
        #pragma unroll
        for (int bb = 0; bb < 8; bb++) {
            out0[(bb * 64 + g) * 64 + lane]      = v0;
            out0[(bb * 64 + g) * 64 + 32 + lane] = v1;
        }
    }

    // ---- phase 1: gather + LN embd1 (8 rows) ----
    for (int r = 0; r < 8; r++) {
        int row = row0 + r;
        int s   = row & 511;
        int tk  = tok[row], ty = tty[row];
        const float* pw = Wword + (size_t)tk * 768;
        const float* pt = Wtype + (size_t)ty * 768;
        const float* pa = Wabs  + (size_t)s  * 768;
        float v0 = pw[t      ] + pt[t      ] + pa[t      ];
        float v1 = pw[t + 256] + pt[t + 256] + pa[t + 256];
        float v2 = pw[t + 512] + pt[t + 512] + pa[t + 512];
        sm.e1.sx[r][t] = v0; sm.e1.sx[r][t + 256] = v1; sm.e1.sx[r][t + 512] = v2;

        float s1 = v0 + v1 + v2;
        float q1 = v0 * v0 + v1 * v1 + v2 * v2;
        #pragma unroll
        for (int o = 16; o; o >>= 1) {
            s1 += __shfl_down_sync(0xffffffffu, s1, o);
            q1 += __shfl_down_sync(0xffffffffu, q1, o);
        }
        if (lane == 0) { sm.e1.wsum[warp] = s1; sm.e1.wsq[warp] = q1; }
        __syncthreads();
        if (t == 0) {
            float S = 0.f, Q = 0.f;
            #pragma unroll
            for (int w = 0; w < 8; w++) { S += sm.e1.wsum[w]; Q += sm.e1.wsq[w]; }
            float mean = S * (1.0f / 768.0f);
            float var  = Q * (1.0f / 768.0f) - mean * mean;
            sm.e1.stat[0] = mean; sm.e1.stat[1] = rsqrtf(var + LN_EPS);
        }
        __syncthreads();
        float mean = sm.e1.stat[0], inv = sm.e1.stat[1];
        float* o = out1 + (size_t)row * 768;
        o[t      ] = (v0 - mean) * inv;
        o[t + 256] = (v1 - mean) * inv;
        o[t + 512] = (v2 - mean) * inv;
        __syncthreads();
    }

    // ---- phase 2: diag GEMV, 8-row register blocking (R2-exact) ----
    float acc0[8], acc1[8];
    #pragma unroll
    for (int r = 0; r < 8; r++) { acc0[r] = 0.f; acc1[r] = 0.f; }

    for (int c = 0; c < 12; c++) {
        __syncthreads();
        for (int e = t; e < 64 * 64; e += 256) {
            int k = e & 63, d = e >> 6;
            sm.e1.sWd[k][d] = Wdiag[(size_t)d * 768 + c * 64 + k];
        }
        __syncthreads();
        int kbase = warp * 8;
        #pragma unroll
        for (int kk = 0; kk < 8; kk++) {
            float w0 = sm.e1.sWd[kbase + kk][lane];
            float w1 = sm.e1.sWd[kbase + kk][lane + 32];
            int kg = c * 64 + kbase + kk;
            #pragma unroll
            for (int r = 0; r < 8; r++) {
                float xv = sm.e1.sx[r][kg];
                acc0[r] += xv * w0;
                acc1[r] += xv * w1;
            }
        }
    }

    // cross-warp reduction
    __syncthreads();
    #pragma unroll
    for (int r = 0; r < 8; r++) {
        sm.e1.sred[warp][r][lane]      = acc0[r];
        sm.e1.sred[warp][r][lane + 32] = acc1[r];
    }
    __syncthreads();
    for (int o = t; o < 512; o += 256) {
        int r = o >> 6, d = o & 63;
        float s = 0.f;
        #pragma unroll
        for (int w = 0; w < 8; w++) s += sm.e1.sred[w][r][d];
        sm.e1.sy[r][d] = s + Wrel[d] + bdiag[d];
    }
    __syncthreads();

    // LN per diag row + store to embd2 diagonal
    {
        float y0 = sm.e1.sy[warp][lane];
        float y1 = sm.e1.sy[warp][lane + 32];
        float S = y0 + y1, Q = y0 * y0 + y1 * y1;
        #pragma unroll
        for (int o = 16; o; o >>= 1) {
            S += __shfl_xor_sync(0xffffffffu, S, o);
            Q += __shfl_xor_sync(0xffffffffu, Q, o);
        }
        float mean = S * (1.0f / 64.0f);
        float inv  = rsqrtf(Q * (1.0f / 64.0f) - mean * mean + LN_EPS);
        int row = row0 + warp;
        int s   = row & 511;
        float* od = out2 + ((size_t)row * 512 + s) * 64;
        od[lane]      = (y0 - mean) * inv;
        od[lane + 32] = (y1 - mean) * inv;
    }
}

// ---------------------------------------------------------------------------
extern "C" void kernel_launch(void* const* d_in, const int* in_sizes, int n_in,
                              void* d_out, int out_size) {
    const int*   tok   = (const int*)d_in[0];
    const int*   tty   = (const int*)d_in[1];
    const float* Wword = (const float*)d_in[2];
    const float* Wtype = (const float*)d_in[3];
    const float* Wabs  = (const float*)d_in[4];
    const float* Wrel  = (const float*)d_in[5];
    const float* Wglob = (const float*)d_in[6];
    const float* Wdiag = (const float*)d_in[7];
    const float* bdiag = (const float*)d_in[8];

    float* out  = (float*)d_out;
    float* out0 = out;                      // [8,64,64]
    float* out1 = out0 + 8 * 64 * 64;       // [8,512,768]
    float* out2 = out1 + 8 * 512 * 768;     // [8,512,512,64]

    k_fused<<<2560, 256>>>(tok, tty, Wword, Wtype, Wabs, Wrel, Wglob, Wdiag,
                           bdiag, out0, out1, out2);
}

// round 10
// speedup vs baseline: 1.7079x; 1.0200x over previous
#include <cuda_runtime.h>

#define LN_EPS 1e-12f

// ===========================================================================
// Kernel A: embd2 fill (store-bound role). 2048 blocks, 2 rows each.
// ===========================================================================
__global__ void k_embd2(const int* __restrict__ tty,
                        const float* __restrict__ Wrel,
                        float* __restrict__ out2) {
    __shared__ float lnrel[130 * 64];
    __shared__ int   sid[2][512];
    __shared__ int   stype[512];

    const int t    = threadIdx.x;
    const int warp = t >> 5, lane = t & 31;
    const int R0   = blockIdx.x * 2;          // rows R0, R0+1 (same batch)
    const int b    = R0 >> 9;
    const int i0   = R0 & 511;

    // LN(W_rel) table: warp-per-row, 17 passes
    for (int p = 0; p < 17; p++) {
        int row = p * 8 + warp;
        if (row < 130) {
            float x0 = Wrel[row * 64 + lane];
            float x1 = Wrel[row * 64 + 32 + lane];
            float s = x0 + x1, q = x0 * x0 + x1 * x1;
            #pragma unroll
            for (int o = 16; o; o >>= 1) {
                s += __shfl_xor_sync(0xffffffffu, s, o);
                q += __shfl_xor_sync(0xffffffffu, q, o);
            }
            float mean = s * (1.0f / 64.0f);
            float inv  = rsqrtf(q * (1.0f / 64.0f) - mean * mean + LN_EPS);
            lnrel[row * 64 + lane]      = (x0 - mean) * inv;
            lnrel[row * 64 + 32 + lane] = (x1 - mean) * inv;
        }
    }
    for (int j = t; j < 512; j += 256) stype[j] = tty[b * 512 + j];
    __syncthreads();

    for (int rr = 0; rr < 2; rr++) {
        int i  = i0 + rr;
        int ti = stype[i];
        for (int j = t; j < 512; j += 256) {
            int id;
            if (j == i)               id = -1;           // diag: skip
            else if (i == 0)          id = 128;
            else if (j == 0)          id = 129;
            else if (stype[j] != ti)  id = 64;
            else {
                int d = i - j;
                id = (d > 0) ? 128 - min(d, 63) : min(-d, 63);
            }
            sid[rr][j] = (id < 0) ? -1 : (id << 4);      // float4 offset
        }
    }
    __syncthreads();

    // hot loop: explicit 4-wide batching for store-stream MLP
    const float4* ln4 = reinterpret_cast<const float4*>(lnrel);
    float4* outp = reinterpret_cast<float4*>(out2) + (size_t)R0 * (512 * 16);
    const int* sidp = &sid[0][0];
    const int d4  = t & 15;
    const int jr0 = t >> 4;
    #pragma unroll 4
    for (int g = 0; g < 16; g++) {
        int base = g * 64 + jr0;
        int s0 = sidp[base];
        int s1 = sidp[base + 16];
        int s2 = sidp[base + 32];
        int s3 = sidp[base + 48];
        float4 v0 = ln4[max(s0, 0) + d4];
        float4 v1 = ln4[max(s1, 0) + d4];
        float4 v2 = ln4[max(s2, 0) + d4];
        float4 v3 = ln4[max(s3, 0) + d4];
        float4* o = outp + base * 16 + d4;
        if (s0 >= 0) __stcs(o,           v0);
        if (s1 >= 0) __stcs(o + 16 * 16, v1);
        if (s2 >= 0) __stcs(o + 32 * 16, v2);
        if (s3 >= 0) __stcs(o + 48 * 16, v3);
    }
}

// ===========================================================================
// Kernel B: compute role. 512 blocks, 8 rows each (embd1 + diag + out0).
// ===========================================================================
__global__ void __launch_bounds__(256) k_comp(
    const int* __restrict__ tok, const int* __restrict__ tty,
    const float* __restrict__ Wword, const float* __restrict__ Wtype,
    const float* __restrict__ Wabs,  const float* __restrict__ Wrel,
    const float* __restrict__ Wglob, const float* __restrict__ Wdiag,
    const float* __restrict__ bdiag,
    float* __restrict__ out0, float* __restrict__ out1,
    float* __restrict__ out2) {

    __shared__ float sx[8][768];
    __shared__ union {
        float sWd[64][65];
        float sred[8][8][64];
    } u;
    __shared__ float sy[8][64];
    __shared__ float wsum[8], wsq[8];
    __shared__ float stat[2];

    const int t    = threadIdx.x;
    const int warp = t >> 5, lane = t & 31;
    const int cid  = blockIdx.x;
    const int row0 = cid * 8;

    // out0 duty: blocks 0..7 LN 8 rows of W_glob each, broadcast x8 batches
    if (cid < 8) {
        int g = cid * 8 + warp;
        float x0 = Wglob[g * 64 + lane];
        float x1 = Wglob[g * 64 + 32 + lane];
        float s = x0 + x1, q = x0 * x0 + x1 * x1;
        #pragma unroll
        for (int o = 16; o; o >>= 1) {
            s += __shfl_xor_sync(0xffffffffu, s, o);
            q += __shfl_xor_sync(0xffffffffu, q, o);
        }
        float mean = s * (1.0f / 64.0f);
        float inv  = rsqrtf(q * (1.0f / 64.0f) - mean * mean + LN_EPS);
        float v0 = (x0 - mean) * inv, v1 = (x1 - mean) * inv;
        #pragma unroll
        for (int bb = 0; bb < 8; bb++) {
            out0[(bb * 64 + g) * 64 + lane]      = v0;
            out0[(bb * 64 + g) * 64 + 32 + lane] = v1;
        }
    }

    // ---- phase 1: gather + LN embd1 (8 rows) ----
    for (int r = 0; r < 8; r++) {
        int row = row0 + r;
        int s   = row & 511;
        int tk  = tok[row], ty = tty[row];
        const float* pw = Wword + (size_t)tk * 768;
        const float* pt = Wtype + (size_t)ty * 768;
        const float* pa = Wabs  + (size_t)s  * 768;
        float v0 = pw[t      ] + pt[t      ] + pa[t      ];
        float v1 = pw[t + 256] + pt[t + 256] + pa[t + 256];
        float v2 = pw[t + 512] + pt[t + 512] + pa[t + 512];
        sx[r][t] = v0; sx[r][t + 256] = v1; sx[r][t + 512] = v2;

        float s1 = v0 + v1 + v2;
        float q1 = v0 * v0 + v1 * v1 + v2 * v2;
        #pragma unroll
        for (int o = 16; o; o >>= 1) {
            s1 += __shfl_down_sync(0xffffffffu, s1, o);
            q1 += __shfl_down_sync(0xffffffffu, q1, o);
        }
        if (lane == 0) { wsum[warp] = s1; wsq[warp] = q1; }
        __syncthreads();
        if (t == 0) {
            float S = 0.f, Q = 0.f;
            #pragma unroll
            for (int w = 0; w < 8; w++) { S += wsum[w]; Q += wsq[w]; }
            float mean = S * (1.0f / 768.0f);
            float var  = Q * (1.0f / 768.0f) - mean * mean;
            stat[0] = mean; stat[1] = rsqrtf(var + LN_EPS);
        }
        __syncthreads();
        float mean = stat[0], inv = stat[1];
        float* o = out1 + (size_t)row * 768;
        o[t      ] = (v0 - mean) * inv;
        o[t + 256] = (v1 - mean) * inv;
        o[t + 512] = (v2 - mean) * inv;
        __syncthreads();
    }

    // ---- phase 2: diag GEMV, 8-row register blocking ----
    float acc0[8], acc1[8];
    #pragma unroll
    for (int r = 0; r < 8; r++) { acc0[r] = 0.f; acc1[r] = 0.f; }

    for (int c = 0; c < 12; c++) {
        __syncthreads();
        for (int e = t; e < 64 * 64; e += 256) {
            int k = e & 63, d = e >> 6;
            u.sWd[k][d] = Wdiag[(size_t)d * 768 + c * 64 + k];
        }
        __syncthreads();
        int kbase = warp * 8;
        #pragma unroll
        for (int kk = 0; kk < 8; kk++) {
            float w0 = u.sWd[kbase + kk][lane];
            float w1 = u.sWd[kbase + kk][lane + 32];
            int kg = c * 64 + kbase + kk;
            #pragma unroll
            for (int r = 0; r < 8; r++) {
                float xv = sx[r][kg];
                acc0[r] += xv * w0;
                acc1[r] += xv * w1;
            }
        }
    }

    __syncthreads();
    #pragma unroll
    for (int r = 0; r < 8; r++) {
        u.sred[warp][r][lane]      = acc0[r];
        u.sred[warp][r][lane + 32] = acc1[r];
    }
    __syncthreads();
    for (int o = t; o < 512; o += 256) {
        int r = o >> 6, d = o & 63;
        float s = 0.f;
        #pragma unroll
        for (int w = 0; w < 8; w++) s += u.sred[w][r][d];
        sy[r][d] = s + Wrel[d] + bdiag[d];
    }
    __syncthreads();

    {
        float y0 = sy[warp][lane];
        float y1 = sy[warp][lane + 32];
        float S = y0 + y1, Q = y0 * y0 + y1 * y1;
        #pragma unroll
        for (int o = 16; o; o >>= 1) {
            S += __shfl_xor_sync(0xffffffffu, S, o);
            Q += __shfl_xor_sync(0xffffffffu, Q, o);
        }
        float mean = S * (1.0f / 64.0f);
        float inv  = rsqrtf(Q * (1.0f / 64.0f) - mean * mean + LN_EPS);
        int row = row0 + warp;
        int s   = row & 511;
        float* od = out2 + ((size_t)row * 512 + s) * 64;
        od[lane]      = (y0 - mean) * inv;
        od[lane + 32] = (y1 - mean) * inv;
    }
}

// ---------------------------------------------------------------------------
extern "C" void kernel_launch(void* const* d_in, const int* in_sizes, int n_in,
                              void* d_out, int out_size) {
    const int*   tok   = (const int*)d_in[0];
    const int*   tty   = (const int*)d_in[1];
    const float* Wword = (const float*)d_in[2];
    const float* Wtype = (const float*)d_in[3];
    const float* Wabs  = (const float*)d_in[4];
    const float* Wrel  = (const float*)d_in[5];
    const float* Wglob = (const float*)d_in[6];
    const float* Wdiag = (const float*)d_in[7];
    const float* bdiag = (const float*)d_in[8];

    float* out  = (float*)d_out;
    float* out0 = out;                      // [8,64,64]
    float* out1 = out0 + 8 * 64 * 64;       // [8,512,768]
    float* out2 = out1 + 8 * 512 * 768;     // [8,512,512,64]

    // fork-join: compute kernel runs concurrently on a second stream
    cudaStream_t s2;
    cudaEvent_t  efork, ejoin;
    cudaStreamCreateWithFlags(&s2, cudaStreamNonBlocking);
    cudaEventCreateWithFlags(&efork, cudaEventDisableTiming);
    cudaEventCreateWithFlags(&ejoin, cudaEventDisableTiming);

    cudaEventRecord(efork, 0);
    cudaStreamWaitEvent(s2, efork, 0);

    k_comp<<<512, 256, 0, s2>>>(tok, tty, Wword, Wtype, Wabs, Wrel, Wglob,
                                Wdiag, bdiag, out0, out1, out2);
    cudaEventRecord(ejoin, s2);

    k_embd2<<<2048, 256>>>(tty, Wrel, out2);

    cudaStreamWaitEvent(0, ejoin, 0);
}